// round 3
// baseline (speedup 1.0000x reference)
#include <cuda_runtime.h>
#include <cuda_fp16.h>
#include <cstdint>
#include <math.h>

#define Bn 256
#define Tn 4096
#define BT (Bn*Tn)

__device__ uint4    g_gi[BT];   // per (b,t): CR,CZ,CN (half2), pad
__device__ float    g_q [BT];   // emission ratio exp(l1-l0)
__device__ unsigned g_h [BT];   // GRU hidden half2

static __device__ __forceinline__ __half2 tanh2(__half2 x){
    unsigned xi = *reinterpret_cast<unsigned*>(&x), ri;
    asm("tanh.approx.f16x2 %0, %1;" : "=r"(ri) : "r"(xi));
    return *reinterpret_cast<__half2*>(&ri);
}

// ========================= K1: prep =========================
__global__ __launch_bounds__(256) void prep_kernel(
    const float* __restrict__ x,
    const float* __restrict__ fc1w, const float* __restrict__ fc1b,
    const float* __restrict__ fc2w, const float* __restrict__ fc2b,
    const float* __restrict__ wih,  const float* __restrict__ bih,
    const float* __restrict__ bhh)
{
    float W1[24], B1[8], DW[8], WI[18], BI[6], BH[4];
#pragma unroll
    for (int i=0;i<24;i++) W1[i]=fc1w[i];
#pragma unroll
    for (int i=0;i<8;i++){ B1[i]=fc1b[i]; DW[i]=fc2w[8+i]-fc2w[i]; }
#pragma unroll
    for (int i=0;i<18;i++) WI[i]=wih[i];
#pragma unroll
    for (int i=0;i<6;i++) BI[i]=bih[i];
#pragma unroll
    for (int i=0;i<4;i++) BH[i]=bhh[i];
    float db = fc2b[1]-fc2b[0];

    int base = blockIdx.x*256 + threadIdx.x;
    for (int idx = base; idx < BT; idx += 524288) {
        float x0=x[idx*3], x1=x[idx*3+1], x2=x[idx*3+2];
        float d = db;
#pragma unroll
        for (int j=0;j<8;j++){
            float u = fmaf(W1[j*3],x0,fmaf(W1[j*3+1],x1,fmaf(W1[j*3+2],x2,B1[j])));
            d = fmaf(DW[j], tanhf(u), d);
        }
        g_q[idx] = __expf(d);

        float gg[6];
#pragma unroll
        for (int j=0;j<6;j++)
            gg[j] = fmaf(WI[j*3],x0,fmaf(WI[j*3+1],x1,fmaf(WI[j*3+2],x2,BI[j])));
        __half2 CR = __floats2half2_rn(0.5f*(gg[0]+BH[0]), 0.5f*(gg[1]+BH[1]));
        __half2 CZ = __floats2half2_rn(0.5f*(gg[2]+BH[2]), 0.5f*(gg[3]+BH[3]));
        __half2 CN = __floats2half2_rn(gg[4], gg[5]);
        uint4 pk;
        pk.x=*reinterpret_cast<unsigned*>(&CR);
        pk.y=*reinterpret_cast<unsigned*>(&CZ);
        pk.z=*reinterpret_cast<unsigned*>(&CN);
        pk.w=0u;
        g_gi[idx]=pk;
    }
}

// ========================= K2: GRU (chunked, fp16x2) =========================
__global__ __launch_bounds__(128) void gru_kernel(
    const float* __restrict__ whh, const float* __restrict__ bhh)
{
    int gid = blockIdx.x*128 + threadIdx.x;   // 16384 = 256 b * 64 chunks
    int b = gid >> 6, c = gid & 63;

    float w[12];
#pragma unroll
    for (int i=0;i<12;i++) w[i]=whh[i];
    __half2 WRA=__floats2half2_rn(0.5f*w[0],0.5f*w[2]), WRB=__floats2half2_rn(0.5f*w[1],0.5f*w[3]);
    __half2 WZA=__floats2half2_rn(0.5f*w[4],0.5f*w[6]), WZB=__floats2half2_rn(0.5f*w[5],0.5f*w[7]);
    __half2 WNA=__floats2half2_rn(w[8],w[10]),          WNB=__floats2half2_rn(w[9],w[11]);
    __half2 BN =__floats2half2_rn(bhh[4],bhh[5]);
    const __half2 H05=__floats2half2_rn(0.5f,0.5f), HM05=__floats2half2_rn(-0.5f,-0.5f);

    int t0 = c*64;
    int tstart = (c==0) ? 0 : (t0-64);
    int nwarm  = t0 - tstart;
    const uint4* gp = g_gi + (size_t)b*Tn;
    unsigned*    hp = g_h  + (size_t)b*Tn + tstart;

    uint4 ring[8];
#pragma unroll
    for (int i=0;i<8;i++) ring[i]=gp[tstart+i];

    __half2 h = __floats2half2_rn(0.f,0.f);
    for (int s=0; s<128; s+=8) {
#pragma unroll
        for (int i=0;i<8;i++){
            uint4 gv = ring[i];
            int pf = tstart+s+i+8;
            ring[i] = gp[(pf < tstart+128) ? pf : tstart];

            __half2 CR=*reinterpret_cast<__half2*>(&gv.x);
            __half2 CZ=*reinterpret_cast<__half2*>(&gv.y);
            __half2 CN=*reinterpret_cast<__half2*>(&gv.z);
            __half2 h0b=__half2half2(__low2half(h)), h1b=__half2half2(__high2half(h));

            __half2 aR=__hfma2(h0b,WRA,__hfma2(h1b,WRB,CR));
            __half2 aZ=__hfma2(h0b,WZA,__hfma2(h1b,WZB,CZ));
            __half2 GN=__hfma2(h0b,WNA,__hfma2(h1b,WNB,BN));
            __half2 tr=tanh2(aR), tz=tanh2(aZ);
            __half2 Ch=__hmul2(GN,H05);
            __half2 aN=__hfma2(tr,Ch,__hadd2(CN,Ch));
            __half2 tn=tanh2(aN);
            __half2 A =__hfma2(tz,HM05,H05);
            __half2 hh=__hmul2(h,H05);
            __half2 ZH=__hfma2(tz,hh,hh);
            h = __hfma2(tn,A,ZH);

            int tt = s+i;
            if (tt>=nwarm && tt<nwarm+64) hp[tt]=*reinterpret_cast<unsigned*>(&h);
        }
    }
}

// ========================= K3: HMM scan + epilogue =========================
// smem floats: sq[4096] sra[4096] srb[4096] sP[256] sBf[64] sEb[64] = 50688 B
__global__ __launch_bounds__(256) void hmm_kernel(
    const float* __restrict__ Qseq,
    const float* __restrict__ lpi, const float* __restrict__ lAg,
    const float* __restrict__ Wgp, const float* __restrict__ byp,
    float* __restrict__ out)
{
    extern __shared__ float sm[];
    float* sq  = sm;
    float* sra = sm+4096;
    float* srb = sm+8192;
    float* sP  = sm+12288;
    float* sBf = sm+12544;
    float* sEb = sm+12608;

    int b = blockIdx.x, tid = threadIdx.x;

    float l00=lAg[0],l01=lAg[1],l10=lAg[2],l11=lAg[3];
    float m0=fmaxf(l00,l01), m1=fmaxf(l10,l11);
    float e00=__expf(l00-m0), e01=__expf(l01-m0), e10=__expf(l10-m1), e11=__expf(l11-m1);
    float i0=1.f/(e00+e01), i1=1.f/(e10+e11);
    float a00=e00*i0, a01=e01*i0, a10=e10*i1, a11=e11*i1;
    float p1=__expf(lpi[1]-lpi[0]);

    float WG[20], BY[4];
#pragma unroll
    for (int i=0;i<20;i++) WG[i]=Wgp[i];
#pragma unroll
    for (int i=0;i<4;i++) BY[i]=byp[i];

    { const float4* qg=reinterpret_cast<const float4*>(g_q+(size_t)b*Tn);
      float4* s4=reinterpret_cast<float4*>(sq);
      for (int i=tid;i<1024;i+=256) s4[i]=qg[i]; }
    __syncthreads();

    // stage 1: chunk products (chunk 0 over t=1..63)
    if (tid < 64) {
        int c=tid;
        float p00=1.f,p01=0.f,p10=0.f,p11=1.f;
        int ts=(c==0)?1:c*64, te=c*64+63;
        for (int t=ts;t<=te;t++){
            float qv=sq[t], qa01=a01*qv, qa11=a11*qv;
            float n00=p00*a00+p01*a10, n01=p00*qa01+p01*qa11;
            float n10=p10*a00+p11*a10, n11=p10*qa01+p11*qa11;
            p00=n00;p01=n01;p10=n10;p11=n11;
            if ((t&15)==0){ float s=1.f/(p00+p01+p10+p11); p00*=s;p01*=s;p10*=s;p11*=s; }
        }
        float s=1.f/(p00+p01+p10+p11);
        sP[c*4]=p00*s; sP[c*4+1]=p01*s; sP[c*4+2]=p10*s; sP[c*4+3]=p11*s;
    }
    __syncthreads();

    // stage 2: boundary ratio chains
    if (tid == 0) {
        float r = p1*sq[0]; sBf[0]=r;
        for (int c=0;c<63;c++){
            const float* P=sP+c*4;
            r = (P[1]+r*P[3]) / (P[0]+r*P[2]);
            sBf[c+1]=r;
        }
    } else if (tid == 32) {
        float r = 1.f; sEb[63]=1.f;
        for (int c=62;c>=0;c--){
            const float* P=sP+(c+1)*4;
            r = (P[2]+P[3]*r) / (P[0]+P[1]*r);
            sEb[c]=r;
        }
    }
    __syncthreads();

    // stage 3: within-chunk ratio replay (threads 0-63 fwd, 64-127 bwd)
    if (tid < 64) {
        int c=tid; float r=sBf[c];
        int ts, te=c*64+63;
        if (c==0){ sra[0]=r; ts=1; } else ts=c*64;
        for (int t=ts;t<=te;t++){
            r = sq[t]*(a01+a11*r) / (a00+a10*r);
            sra[t]=r;
        }
    } else if (tid < 128) {
        int c=tid-64; float r=sEb[c];
        srb[c*64+63]=r;
        for (int t=c*64+62;t>=c*64;t--){
            float w=sq[t+1]*r;
            r = (a10+a11*w) / (a00+a01*w);
            srb[t]=r;
        }
    }
    __syncthreads();

    // stage 4: epilogue
    const size_t OFF1=(size_t)Bn*Tn*2, OFF2=(size_t)Bn*Tn*7;
    for (int t=tid; t<Tn; t+=256) {
        size_t bt=(size_t)b*Tn+t;
        float p = sra[t]*srb[t];
        float lp1 = __logf(p), l1p = __logf(1.f+p);
        float lg0=-l1p, lg1=lp1-l1p;
        float gm1=p/(1.f+p), gm0=1.f-gm1;

        unsigned hv=g_h[bt];
        __half2 h2=*reinterpret_cast<__half2*>(&hv);
        float h0=__low2float(h2), h1=__high2float(h2);

        float gk[2][5];
#pragma unroll
        for (int k=0;k<2;k++){
            float wv[5], mx=-1e30f;
#pragma unroll
            for (int a=0;a<5;a++){ wv[a]=fmaf(h0,WG[k*10+a],h1*WG[k*10+5+a]); mx=fmaxf(mx,wv[a]); }
            float s=0.f;
#pragma unroll
            for (int a=0;a<5;a++){ wv[a]=__expf(wv[a]-mx); s+=wv[a]; }
            float is=1.f/s;
#pragma unroll
            for (int a=0;a<5;a++) gk[k][a]=wv[a]*is;
        }
        float gv[5];
#pragma unroll
        for (int a=0;a<5;a++) gv[a]=fmaf(gm0,gk[0][a],gm1*gk[1][a]);

        const float2* Qp=reinterpret_cast<const float2*>(Qseq+bt*10);
        float V0=fmaf(gm0,BY[0],gm1*BY[2]);
        float V1=fmaf(gm0,BY[1],gm1*BY[3]);
#pragma unroll
        for (int a=0;a<5;a++){
            float2 qy=Qp[a];
            V0=fmaf(gv[a],qy.x,V0);
            V1=fmaf(gv[a],qy.y,V1);
        }
        float mv=fmaxf(V0,V1);
        float lse=mv+__logf(__expf(V0-mv)+__expf(V1-mv));

        out[bt*2]=V0-lse; out[bt*2+1]=V1-lse;
        float* go=out+OFF1+bt*5;
#pragma unroll
        for (int a=0;a<5;a++) go[a]=gv[a];
        out[OFF2+bt*2]=lg0; out[OFF2+bt*2+1]=lg1;
    }
}

// ========================= launch =========================
extern "C" void kernel_launch(void* const* d_in, const int* in_sizes, int n_in,
                              void* d_out, int out_size)
{
    const float* x    =(const float*)d_in[0];
    const float* Qseq =(const float*)d_in[1];
    const float* lpi  =(const float*)d_in[2];
    const float* lA   =(const float*)d_in[3];
    const float* fc1w =(const float*)d_in[4];
    const float* fc1b =(const float*)d_in[5];
    const float* fc2w =(const float*)d_in[6];
    const float* fc2b =(const float*)d_in[7];
    const float* wih  =(const float*)d_in[8];
    const float* whh  =(const float*)d_in[9];
    const float* bih  =(const float*)d_in[10];
    const float* bhh  =(const float*)d_in[11];
    const float* Wg   =(const float*)d_in[12];
    const float* by   =(const float*)d_in[13];
    float* out=(float*)d_out;

    static bool attr_set=false;
    if (!attr_set){
        cudaFuncSetAttribute(hmm_kernel, cudaFuncAttributeMaxDynamicSharedMemorySize, 50688);
        attr_set=true;
    }

    prep_kernel<<<2048,256>>>(x,fc1w,fc1b,fc2w,fc2b,wih,bih,bhh);
    gru_kernel<<<128,128>>>(whh,bhh);
    hmm_kernel<<<256,256,50688>>>(Qseq,lpi,lA,Wg,by,out);
}

// round 4
// speedup vs baseline: 1.0485x; 1.0485x over previous
#include <cuda_runtime.h>
#include <cuda_fp16.h>
#include <cstdint>
#include <math.h>

#define Bn 256
#define Tn 4096
#define BT (Bn*Tn)

__device__ uint4    g_gi[BT];   // per (b,t): CR,CZ,CN (half2), pad
__device__ float    g_q [BT];   // emission ratio exp(l1-l0)
__device__ unsigned g_h [BT];   // GRU hidden half2

static __device__ __forceinline__ __half2 tanh2(__half2 x){
    unsigned xi = *reinterpret_cast<unsigned*>(&x), ri;
    asm("tanh.approx.f16x2 %0, %1;" : "=r"(ri) : "r"(xi));
    return *reinterpret_cast<__half2*>(&ri);
}
static __device__ __forceinline__ float tanhap(float x){
    float y; asm("tanh.approx.f32 %0, %1;" : "=f"(y) : "f"(x)); return y;
}

// ========================= K1: prep =========================
__global__ __launch_bounds__(256) void prep_kernel(
    const float* __restrict__ x,
    const float* __restrict__ fc1w, const float* __restrict__ fc1b,
    const float* __restrict__ fc2w, const float* __restrict__ fc2b,
    const float* __restrict__ wih,  const float* __restrict__ bih,
    const float* __restrict__ bhh)
{
    float W1[24], B1[8], DW[8], WI[18], BI[6], BH[4];
#pragma unroll
    for (int i=0;i<24;i++) W1[i]=fc1w[i];
#pragma unroll
    for (int i=0;i<8;i++){ B1[i]=fc1b[i]; DW[i]=fc2w[8+i]-fc2w[i]; }
#pragma unroll
    for (int i=0;i<18;i++) WI[i]=wih[i];
#pragma unroll
    for (int i=0;i<6;i++) BI[i]=bih[i];
#pragma unroll
    for (int i=0;i<4;i++) BH[i]=bhh[i];
    float db = fc2b[1]-fc2b[0];

    int idx = blockIdx.x*256 + threadIdx.x;   // 1M threads, 1 item each
    float x0=x[idx*3], x1=x[idx*3+1], x2=x[idx*3+2];

    float d = db;
#pragma unroll
    for (int j=0;j<8;j++){
        float u = fmaf(W1[j*3],x0,fmaf(W1[j*3+1],x1,fmaf(W1[j*3+2],x2,B1[j])));
        d = fmaf(DW[j], tanhap(u), d);
    }
    g_q[idx] = __expf(d);

    float gg[6];
#pragma unroll
    for (int j=0;j<6;j++)
        gg[j] = fmaf(WI[j*3],x0,fmaf(WI[j*3+1],x1,fmaf(WI[j*3+2],x2,BI[j])));
    __half2 CR = __floats2half2_rn(0.5f*(gg[0]+BH[0]), 0.5f*(gg[1]+BH[1]));
    __half2 CZ = __floats2half2_rn(0.5f*(gg[2]+BH[2]), 0.5f*(gg[3]+BH[3]));
    __half2 CN = __floats2half2_rn(gg[4], gg[5]);
    uint4 pk;
    pk.x=*reinterpret_cast<unsigned*>(&CR);
    pk.y=*reinterpret_cast<unsigned*>(&CZ);
    pk.z=*reinterpret_cast<unsigned*>(&CN);
    pk.w=0u;
    g_gi[idx]=pk;
}

// ========================= K2: GRU (chunked, fp16x2) =========================
__global__ __launch_bounds__(128) void gru_kernel(
    const float* __restrict__ whh, const float* __restrict__ bhh)
{
    int gid = blockIdx.x*128 + threadIdx.x;   // 16384 = 256 b * 64 chunks
    int b = gid >> 6, c = gid & 63;

    float w[12];
#pragma unroll
    for (int i=0;i<12;i++) w[i]=whh[i];
    __half2 WRA=__floats2half2_rn(0.5f*w[0],0.5f*w[2]), WRB=__floats2half2_rn(0.5f*w[1],0.5f*w[3]);
    __half2 WZA=__floats2half2_rn(0.5f*w[4],0.5f*w[6]), WZB=__floats2half2_rn(0.5f*w[5],0.5f*w[7]);
    __half2 WNA=__floats2half2_rn(w[8],w[10]),          WNB=__floats2half2_rn(w[9],w[11]);
    __half2 BN =__floats2half2_rn(bhh[4],bhh[5]);
    const __half2 H05=__floats2half2_rn(0.5f,0.5f), HM05=__floats2half2_rn(-0.5f,-0.5f);

    int t0 = c*64;
    int tstart = (c==0) ? 0 : (t0-64);
    int nwarm  = t0 - tstart;
    const uint4* gp = g_gi + (size_t)b*Tn;
    unsigned*    hp = g_h  + (size_t)b*Tn + tstart;

    uint4 ring[8];
#pragma unroll
    for (int i=0;i<8;i++) ring[i]=gp[tstart+i];

    __half2 h = __floats2half2_rn(0.f,0.f);
    for (int s=0; s<128; s+=8) {
#pragma unroll
        for (int i=0;i<8;i++){
            uint4 gv = ring[i];
            int pf = tstart+s+i+8;
            ring[i] = gp[(pf < tstart+128) ? pf : tstart];

            __half2 CR=*reinterpret_cast<__half2*>(&gv.x);
            __half2 CZ=*reinterpret_cast<__half2*>(&gv.y);
            __half2 CN=*reinterpret_cast<__half2*>(&gv.z);
            __half2 h0b=__half2half2(__low2half(h)), h1b=__half2half2(__high2half(h));

            __half2 aR=__hfma2(h0b,WRA,__hfma2(h1b,WRB,CR));
            __half2 aZ=__hfma2(h0b,WZA,__hfma2(h1b,WZB,CZ));
            __half2 GN=__hfma2(h0b,WNA,__hfma2(h1b,WNB,BN));
            __half2 tr=tanh2(aR), tz=tanh2(aZ);
            __half2 Ch=__hmul2(GN,H05);
            __half2 aN=__hfma2(tr,Ch,__hadd2(CN,Ch));
            __half2 tn=tanh2(aN);
            __half2 A =__hfma2(tz,HM05,H05);
            __half2 hh=__hmul2(h,H05);
            __half2 ZH=__hfma2(tz,hh,hh);
            h = __hfma2(tn,A,ZH);

            int tt = s+i;
            if (tt>=nwarm && tt<nwarm+64) hp[tt]=*reinterpret_cast<unsigned*>(&h);
        }
    }
}

// ========================= K3: HMM scan + epilogue =========================
// smem floats: sq[4096] suf svf sbu sbv [4096 ea] sSub[1024] sP[256]
//              sBfU/V[64+64] sEbU/V[64+64] = 22016 floats = 88064 B
#define HMM_SMEM 88064
__global__ __launch_bounds__(256) void hmm_kernel(
    const float* __restrict__ Qseq,
    const float* __restrict__ lpi, const float* __restrict__ lAg,
    const float* __restrict__ Wgp, const float* __restrict__ byp,
    float* __restrict__ out)
{
    extern __shared__ float sm[];
    float* sq   = sm;
    float* suf  = sm+4096;
    float* svf  = sm+8192;
    float* sbu  = sm+12288;
    float* sbv  = sm+16384;
    float* sSub = sm+20480;   // 256*4
    float* sP   = sm+21504;   // 64*4
    float* sBfU = sm+21760;
    float* sBfV = sm+21824;
    float* sEbU = sm+21888;
    float* sEbV = sm+21952;

    int b = blockIdx.x, tid = threadIdx.x;

    float l00=lAg[0],l01=lAg[1],l10=lAg[2],l11=lAg[3];
    float m0=fmaxf(l00,l01), m1=fmaxf(l10,l11);
    float e00=__expf(l00-m0), e01=__expf(l01-m0), e10=__expf(l10-m1), e11=__expf(l11-m1);
    float i0=__fdividef(1.f,e00+e01), i1=__fdividef(1.f,e10+e11);
    float a00=e00*i0, a01=e01*i0, a10=e10*i1, a11=e11*i1;
    float p1=__expf(lpi[1]-lpi[0]);

    float WG[20], BY[4];
#pragma unroll
    for (int i=0;i<20;i++) WG[i]=Wgp[i];
#pragma unroll
    for (int i=0;i<4;i++) BY[i]=byp[i];

    { const float4* qg=reinterpret_cast<const float4*>(g_q+(size_t)b*Tn);
      float4* s4=reinterpret_cast<float4*>(sq);
      for (int i=tid;i<1024;i+=256) s4[i]=qg[i]; }
    __syncthreads();

    // stage 1a: 16-step sub-products (all 256 threads)
    {
        int ts = tid*16, te = ts+16;
        if (tid==0) ts = 1;
        float p00=1.f,p01=0.f,p10=0.f,p11=1.f;
        for (int t=ts;t<te;t++){
            float qv=sq[t], qa01=a01*qv, qa11=a11*qv;
            float n00=fmaf(p01,a10,p00*a00), n01=fmaf(p01,qa11,p00*qa01);
            float n10=fmaf(p11,a10,p10*a00), n11=fmaf(p11,qa11,p10*qa01);
            p00=n00;p01=n01;p10=n10;p11=n11;
        }
        float s=__fdividef(1.f,p00+p01+p10+p11);
        sSub[tid*4]=p00*s; sSub[tid*4+1]=p01*s; sSub[tid*4+2]=p10*s; sSub[tid*4+3]=p11*s;
    }
    __syncthreads();

    // stage 1b: combine 4 sub-products per chunk (threads 0-63)
    if (tid < 64) {
        float p00=sSub[tid*16], p01=sSub[tid*16+1], p10=sSub[tid*16+2], p11=sSub[tid*16+3];
#pragma unroll
        for (int j=1;j<4;j++){
            const float* S = sSub + tid*16 + j*4;
            float n00=fmaf(p01,S[2],p00*S[0]), n01=fmaf(p01,S[3],p00*S[1]);
            float n10=fmaf(p11,S[2],p10*S[0]), n11=fmaf(p11,S[3],p10*S[1]);
            p00=n00;p01=n01;p10=n10;p11=n11;
        }
        float s=__fdividef(1.f,p00+p01+p10+p11);
        sP[tid*4]=p00*s; sP[tid*4+1]=p01*s; sP[tid*4+2]=p10*s; sP[tid*4+3]=p11*s;
    }
    __syncthreads();

    // stage 2: boundary chains (component form, renorm every 8)
    if (tid == 0) {
        float u=1.f, v=p1*sq[0];
        sBfU[0]=u; sBfV[0]=v;
        for (int c=0;c<63;c++){
            const float* P=sP+c*4;
            float nu=fmaf(v,P[2],u*P[0]);
            float nv=fmaf(v,P[3],u*P[1]);
            u=nu; v=nv;
            if ((c&7)==7){ float is=__fdividef(1.f,u+v); u*=is; v*=is; }
            sBfU[c+1]=u; sBfV[c+1]=v;
        }
    } else if (tid == 32) {
        float u=1.f, v=1.f;
        sEbU[63]=1.f; sEbV[63]=1.f;
        for (int c=62;c>=0;c--){
            const float* P=sP+(c+1)*4;
            float nu=fmaf(P[1],v,P[0]*u);
            float nv=fmaf(P[3],v,P[2]*u);
            u=nu; v=nv;
            if ((c&7)==0){ float is=__fdividef(1.f,u+v); u*=is; v*=is; }
            sEbU[c]=u; sEbV[c]=v;
        }
    }
    __syncthreads();

    // stage 3: within-chunk replay (threads 0-63 fwd, 64-127 bwd), component form
    if (tid < 64) {
        int c=tid;
        float u,v; int ts;
        if (c==0){ u=1.f; v=p1*sq[0]; suf[0]=u; svf[0]=v; ts=1; }
        else     { u=sBfU[c]; v=sBfV[c]; ts=c*64; }
        int te=c*64+63;
        for (int t=ts;t<=te;t++){
            float qv=sq[t];
            float nu=fmaf(a10,v,a00*u);
            float nv=qv*fmaf(a11,v,a01*u);
            u=nu; v=nv;
            if ((t&7)==7){ float is=__fdividef(1.f,u+v); u*=is; v*=is; }
            suf[t]=u; svf[t]=v;
        }
    } else if (tid < 128) {
        int c=tid-64;
        float u=sEbU[c], v=sEbV[c];
        int te=c*64+63;
        sbu[te]=u; sbv[te]=v;
        for (int t=te-1;t>=c*64;t--){
            float w=sq[t+1]*v;
            float nu=fmaf(a01,w,a00*u);
            float nv=fmaf(a11,w,a10*u);
            u=nu; v=nv;
            if ((t&7)==0){ float is=__fdividef(1.f,u+v); u*=is; v*=is; }
            sbu[t]=u; sbv[t]=v;
        }
    }
    __syncthreads();

    // stage 4: epilogue
    const size_t OFF1=(size_t)Bn*Tn*2, OFF2=(size_t)Bn*Tn*7;
    for (int t=tid; t<Tn; t+=256) {
        size_t bt=(size_t)b*Tn+t;
        float n0 = suf[t]*sbu[t];
        float n1 = svf[t]*sbv[t];
        float iden = __fdividef(1.f, n0+n1);
        float gm0 = n0*iden, gm1 = n1*iden;
        float lg0 = __logf(gm0), lg1 = __logf(gm1);

        unsigned hv=g_h[bt];
        __half2 h2=*reinterpret_cast<__half2*>(&hv);
        float h0=__low2float(h2), h1=__high2float(h2);

        float gk[2][5];
#pragma unroll
        for (int k=0;k<2;k++){
            float wv[5], mx=-1e30f;
#pragma unroll
            for (int a=0;a<5;a++){ wv[a]=fmaf(h0,WG[k*10+a],h1*WG[k*10+5+a]); mx=fmaxf(mx,wv[a]); }
            float s=0.f;
#pragma unroll
            for (int a=0;a<5;a++){ wv[a]=__expf(wv[a]-mx); s+=wv[a]; }
            float is=__fdividef(1.f,s);
#pragma unroll
            for (int a=0;a<5;a++) gk[k][a]=wv[a]*is;
        }
        float gv[5];
#pragma unroll
        for (int a=0;a<5;a++) gv[a]=fmaf(gm0,gk[0][a],gm1*gk[1][a]);

        const float2* Qp=reinterpret_cast<const float2*>(Qseq+bt*10);
        float V0=fmaf(gm0,BY[0],gm1*BY[2]);
        float V1=fmaf(gm0,BY[1],gm1*BY[3]);
#pragma unroll
        for (int a=0;a<5;a++){
            float2 qy=Qp[a];
            V0=fmaf(gv[a],qy.x,V0);
            V1=fmaf(gv[a],qy.y,V1);
        }
        float mv=fmaxf(V0,V1);
        float lse=mv+__logf(__expf(V0-mv)+__expf(V1-mv));

        out[bt*2]=V0-lse; out[bt*2+1]=V1-lse;
        float* go=out+OFF1+bt*5;
#pragma unroll
        for (int a=0;a<5;a++) go[a]=gv[a];
        out[OFF2+bt*2]=lg0; out[OFF2+bt*2+1]=lg1;
    }
}

// ========================= launch =========================
extern "C" void kernel_launch(void* const* d_in, const int* in_sizes, int n_in,
                              void* d_out, int out_size)
{
    const float* x    =(const float*)d_in[0];
    const float* Qseq =(const float*)d_in[1];
    const float* lpi  =(const float*)d_in[2];
    const float* lA   =(const float*)d_in[3];
    const float* fc1w =(const float*)d_in[4];
    const float* fc1b =(const float*)d_in[5];
    const float* fc2w =(const float*)d_in[6];
    const float* fc2b =(const float*)d_in[7];
    const float* wih  =(const float*)d_in[8];
    const float* whh  =(const float*)d_in[9];
    const float* bih  =(const float*)d_in[10];
    const float* bhh  =(const float*)d_in[11];
    const float* Wg   =(const float*)d_in[12];
    const float* by   =(const float*)d_in[13];
    float* out=(float*)d_out;

    static bool attr_set=false;
    if (!attr_set){
        cudaFuncSetAttribute(hmm_kernel, cudaFuncAttributeMaxDynamicSharedMemorySize, HMM_SMEM);
        attr_set=true;
    }

    prep_kernel<<<4096,256>>>(x,fc1w,fc1b,fc2w,fc2b,wih,bih,bhh);
    gru_kernel<<<128,128>>>(whh,bhh);
    hmm_kernel<<<256,256,HMM_SMEM>>>(Qseq,lpi,lA,Wg,by,out);
}